// round 15
// baseline (speedup 1.0000x reference)
#include <cuda_runtime.h>
#include <stdint.h>

#define SS 2048
#define DDIM 128
#define NT 256

// ===========================================================================
// threefry-2x32, key=(0,42); jax_threefry_partitionable semantics:
// word(i) = hi ^ lo of threefry2x32(key, ctr=(0, i)); keep iff MSB==0.
// ===========================================================================
static __device__ __forceinline__ uint32_t tf_word(uint32_t idx) {
    const uint32_t K0 = 0u, K1 = 42u, K2 = 0x1BD11BDAu ^ 42u;
    uint32_t x0 = 0u + K0, x1 = idx + K1;
#define TFR(R) { x0 += x1; x1 = __funnelshift_l(x1, x1, (R)); x1 ^= x0; }
    TFR(13) TFR(15) TFR(26) TFR(6)
    x0 += K1; x1 += K2 + 1u;
    TFR(17) TFR(29) TFR(16) TFR(24)
    x0 += K2; x1 += K0 + 2u;
    TFR(13) TFR(15) TFR(26) TFR(6)
    x0 += K0; x1 += K1 + 3u;
    TFR(17) TFR(29) TFR(16) TFR(24)
    x0 += K1; x1 += K2 + 4u;
    TFR(13) TFR(15) TFR(26) TFR(6)
    x0 += K2; x1 += K0 + 5u;
#undef TFR
    return x0 ^ x1;
}

// ===========================================================================
// Fallback SIMT kernel (R2, passed at 2073 us)
// ===========================================================================
#define FBM 64
#define FBN 64
#define SQS 132
#define SPS 68

__global__ __launch_bounds__(NT, 2)
void attn_dropout_kernel(const float* __restrict__ Qg,
                         const float* __restrict__ Kg,
                         const float* __restrict__ Vg,
                         float* __restrict__ Og) {
    extern __shared__ float fsm[];
    float* sQ = fsm;
    float* sK = fsm + FBM * SQS;
    float* sV = fsm + 2 * FBM * SQS;
    float* sP = sK;

    const int tid = threadIdx.x;
    const int tx = tid & 15;
    const int ty = tid >> 4;
    const int bh = blockIdx.y;
    const int q0 = blockIdx.x * FBM;

    const float* Qp = Qg + ((size_t)bh * SS + q0) * DDIM;
    const float* Kp = Kg + (size_t)bh * SS * DDIM;
    const float* Vp = Vg + (size_t)bh * SS * DDIM;

    #pragma unroll
    for (int it = 0; it < (FBM * DDIM) / (4 * NT); it++) {
        int e = (tid + it * NT) * 4;
        int r = e >> 7, c = e & 127;
        *(float4*)(sQ + r * SQS + c) = *(const float4*)(Qp + e);
    }

    float acc[4][8];
    #pragma unroll
    for (int j = 0; j < 4; j++)
        #pragma unroll
        for (int i = 0; i < 8; i++) acc[j][i] = 0.f;
    float dsum[4] = {0.f, 0.f, 0.f, 0.f};
    const float scale = 0.08838834764831845f;

    for (int kb = 0; kb < SS / FBN; kb++) {
        __syncthreads();
        const float* Kb = Kp + (size_t)kb * FBN * DDIM;
        const float* Vb = Vp + (size_t)kb * FBN * DDIM;
        #pragma unroll
        for (int it = 0; it < (FBN * DDIM) / (4 * NT); it++) {
            int e = (tid + it * NT) * 4;
            int r = e >> 7, c = e & 127;
            *(float4*)(sK + r * SQS + c) = *(const float4*)(Kb + e);
            *(float4*)(sV + r * DDIM + c) = *(const float4*)(Vb + e);
        }
        __syncthreads();

        float sacc[4][4];
        #pragma unroll
        for (int j = 0; j < 4; j++)
            #pragma unroll
            for (int i = 0; i < 4; i++) sacc[j][i] = 0.f;

        #pragma unroll 4
        for (int d0 = 0; d0 < DDIM; d0 += 4) {
            float4 aq[4], bk[4];
            #pragma unroll
            for (int j = 0; j < 4; j++)
                aq[j] = *(const float4*)(sQ + (4 * ty + j) * SQS + d0);
            #pragma unroll
            for (int i = 0; i < 4; i++)
                bk[i] = *(const float4*)(sK + (tx + 16 * i) * SQS + d0);
            #pragma unroll
            for (int j = 0; j < 4; j++)
                #pragma unroll
                for (int i = 0; i < 4; i++)
                    sacc[j][i] += aq[j].x * bk[i].x + aq[j].y * bk[i].y
                                + aq[j].z * bk[i].z + aq[j].w * bk[i].w;
        }
        __syncthreads();

        uint32_t baseIdx = ((uint32_t)bh << 22) | ((uint32_t)q0 << 11)
                         | (uint32_t)(kb * FBN);
        #pragma unroll
        for (int j = 0; j < 4; j++) {
            #pragma unroll
            for (int i = 0; i < 4; i++) {
                float ex = __expf(sacc[j][i] * scale);
                dsum[j] += ex;
                uint32_t idx = baseIdx + ((uint32_t)(4 * ty + j) << 11)
                             + (uint32_t)(tx + 16 * i);
                uint32_t w = tf_word(idx);
                sP[(4 * ty + j) * SPS + (tx + 16 * i)] = (w & 0x80000000u) ? 0.f : ex;
            }
        }
        __syncthreads();

        #pragma unroll 2
        for (int c0 = 0; c0 < FBN; c0 += 4) {
            float4 p4[4];
            #pragma unroll
            for (int j = 0; j < 4; j++)
                p4[j] = *(const float4*)(sP + (4 * ty + j) * SPS + c0);
            #pragma unroll
            for (int cc = 0; cc < 4; cc++) {
                float bb[8];
                #pragma unroll
                for (int i = 0; i < 8; i++)
                    bb[i] = sV[(c0 + cc) * DDIM + tx + 16 * i];
                #pragma unroll
                for (int j = 0; j < 4; j++) {
                    float pj = ((const float*)&p4[j])[cc];
                    #pragma unroll
                    for (int i = 0; i < 8; i++)
                        acc[j][i] += pj * bb[i];
                }
            }
        }
    }

    __syncthreads();
    #pragma unroll
    for (int j = 0; j < 4; j++)
        sP[(4 * ty + j) * SPS + tx] = dsum[j];
    __syncthreads();

    #pragma unroll
    for (int j = 0; j < 4; j++) {
        float s = 0.f;
        #pragma unroll
        for (int t = 0; t < 16; t++) s += sP[(4 * ty + j) * SPS + t];
        float rs = 2.0f / s;
        size_t orow = ((size_t)bh * SS + (size_t)(q0 + 4 * ty + j)) * DDIM;
        #pragma unroll
        for (int i = 0; i < 8; i++)
            Og[orow + tx + 16 * i] = acc[j][i] * rs;
    }
}

#define FB_SMEM ((2 * FBM * SQS + FBN * DDIM) * 4)

// ===========================================================================
// common helpers
// ===========================================================================
#define BM 128
#define BN 128
#define NKB (SS / BN)            /* 16 kv tiles */

static __device__ __forceinline__ uint32_t smem_u32(const void* p) {
    uint32_t a;
    asm("{ .reg .u64 t; cvta.to.shared.u64 t, %1; cvt.u32.u64 %0, t; }" : "=r"(a) : "l"(p));
    return a;
}
static __device__ __forceinline__ uint32_t swz(uint32_t o) { return o ^ ((o >> 3) & 0x70u); }
// blocked SW128 K-major layout, nrows=128: atom = 8 rows x 64 bf16 (1024B)
static __device__ __forceinline__ uint32_t koff(int n, int k) {
    return ((uint32_t)((n >> 3) + ((k >> 6) << 4)) << 10)
         + (((uint32_t)n & 7u) << 7) + (((uint32_t)k & 63u) << 1);
}
static __device__ __forceinline__ uint32_t prmt_hi(uint32_t a, uint32_t b) {
    uint32_t r; asm("prmt.b32 %0,%1,%2,0x7632;" : "=r"(r) : "r"(a), "r"(b)); return r;
}
static __device__ __forceinline__ float trunc_bf(float x) {
    return __uint_as_float(__float_as_uint(x) & 0xffff0000u);
}
static __device__ __forceinline__ uint32_t pack_bf2(float hi_elem, float lo_elem) {
    uint32_t r; asm("cvt.rn.bf16x2.f32 %0,%1,%2;" : "=r"(r) : "f"(hi_elem), "f"(lo_elem)); return r;
}
static __device__ __forceinline__ float ex2f(float x) {
    float r; asm("ex2.approx.f32 %0, %1;" : "=f"(r) : "f"(x)); return r;
}

// blob tile layout (128KB per tile): KHI 32K | KLO 32K | VHI 32K | VLO 32K
#define TILE_BYTES 131072
#define TILE_K 0
#define TILE_V 65536

// main-kernel smem map
#define SM_K0   0               /* KHI0 | KLO0, 64KB */
#define SM_K1   65536           /* KHI1 | KLO1, 64KB */
#define SM_V    131072          /* VHI | VLO, 64KB */
#define SM_DSUM 196608          /* 128 rows x 8 octs x 4B = 4096 */
#define SM_TPTR 200704
#define SM_MB1  200712
#define SM_MB2  200720
#define TC_SMEM 200768

// pre-converted bf16 hi/lo K/V tiles: 32 bh x 16 tiles x 128KB = 64 MiB
__device__ __align__(1024) unsigned char g_blob[32 * 16 * TILE_BYTES];

// ===========================================================================
// pre-kernel: fp32 K/V -> bf16 hi/lo 128-row tile blobs, MMA-swizzled
// ===========================================================================
__global__ __launch_bounds__(256)
void prep_kv_kernel(const float* __restrict__ Kg, const float* __restrict__ Vg) {
    extern __shared__ __align__(16) unsigned char vs[];   // 64KB: VHI | VLO staged
    const int tile = blockIdx.x;            // bh*16 + kb
    const int bh = tile >> 4, kb = tile & 15;
    const int tid = threadIdx.x;
    const float* Kb = Kg + ((size_t)bh * SS + (size_t)kb * BN) * DDIM;
    const float* Vb = Vg + ((size_t)bh * SS + (size_t)kb * BN) * DDIM;
    unsigned char* out = g_blob + (size_t)tile * TILE_BYTES;

    #pragma unroll
    for (int it = 0; it < 16; it++) {
        int idx = it * 256 + tid;           // float4 index, 4096 total
        int n = idx >> 5, k = (idx & 31) * 4;
        float4 u = *(const float4*)(Kb + n * DDIM + k);
        uint32_t h0 = prmt_hi(__float_as_uint(u.x), __float_as_uint(u.y));
        uint32_t h1 = prmt_hi(__float_as_uint(u.z), __float_as_uint(u.w));
        uint32_t l0 = pack_bf2(u.y - trunc_bf(u.y), u.x - trunc_bf(u.x));
        uint32_t l1 = pack_bf2(u.w - trunc_bf(u.w), u.z - trunc_bf(u.z));
        uint32_t o = swz(koff(n, k));
        *(uint2*)(out + TILE_K + o)         = make_uint2(h0, h1);
        *(uint2*)(out + TILE_K + 32768 + o) = make_uint2(l0, l1);
    }
    int w = tid >> 5, lid = tid & 31;
    #pragma unroll
    for (int i = 0; i < 8; i++) {
        int p = w * 8 + i;                  // kv pair 0..63
        #pragma unroll
        for (int j = 0; j < 4; j++) {
            int d = lid + 32 * j;
            float f0 = Vb[(2 * p) * DDIM + d];
            float f1 = Vb[(2 * p + 1) * DDIM + d];
            uint32_t hw = prmt_hi(__float_as_uint(f0), __float_as_uint(f1));
            uint32_t lw = pack_bf2(f1 - trunc_bf(f1), f0 - trunc_bf(f0));
            uint32_t o = swz(koff(d, 2 * p));
            *(uint32_t*)(vs + o) = hw;
            *(uint32_t*)(vs + 32768 + o) = lw;
        }
    }
    __syncthreads();
    #pragma unroll
    for (int i = 0; i < 16; i++) {
        int e = (i * 256 + tid) * 16;
        *(float4*)(out + TILE_V + e) = *(const float4*)(vs + e);
    }
}

// ===========================================================================
// tcgen05 kernel — only real on the sm_103a pass
// ===========================================================================
#if !defined(__CUDA_ARCH__) || defined(__CUDA_ARCH_FEAT_SM103_ALL) || \
    (defined(__CUDA_ARCH_SPECIFIC__) && (__CUDA_ARCH_SPECIFIC__ >= 1000))
#define TC_PATH_COMPILED 1
#else
#define TC_PATH_COMPILED 0
#endif
#if defined(__CUDA_ARCH__) && TC_PATH_COMPILED
#define TC_DEV 1
#else
#define TC_DEV 0
#endif

// TMEM map: QHI 0, QLO 64, S 128 (128 cols), PHI 256, PLO 320, O 384 (128 cols)
#define T_QHI 0
#define T_QLO 64
#define T_S   128
#define T_PHI 256
#define T_PLO 320
#define T_O   384
#define TMEM_COLS 512

#define IDESC_N128 0x8200490u   /* kind::f16, bf16 x bf16 -> f32, M=128, N=128 */

static constexpr uint64_t DESC_BASE =
    (uint64_t(2) << 61) | (uint64_t(1) << 46) | (uint64_t(64) << 32) | (uint64_t(1) << 16);
static __device__ __forceinline__ uint64_t mk_desc(uint32_t addr) {
    return DESC_BASE | ((uint64_t)(addr >> 4) & 0x3FFFull);
}

#if TC_DEV
static __device__ __forceinline__ void mma_f16(uint32_t d, uint32_t a, uint64_t bdesc,
                                               uint32_t idesc, int acc) {
    asm volatile(
        "{\n\t.reg .pred p;\n\tsetp.ne.u32 p,%5,0;\n\t"
        "tcgen05.mma.cta_group::1.kind::f16 [%0],[%1],%2,%3,{%4,%4,%4,%4},p;\n\t}"
        :: "r"(d), "r"(a), "l"(bdesc), "r"(idesc), "r"(0u), "r"((uint32_t)acc) : "memory");
}

#define TMEM_ALLOC(sa, n)  asm volatile("tcgen05.alloc.cta_group::1.sync.aligned.shared::cta.b32 [%0], %1;" :: "r"(sa), "r"((uint32_t)(n)) : "memory")
#define TMEM_DEALLOC(t, n) asm volatile("tcgen05.dealloc.cta_group::1.sync.aligned.b32 %0, %1;" :: "r"(t), "r"((uint32_t)(n)))
#define TMEM_RELINQ()      asm volatile("tcgen05.relinquish_alloc_permit.cta_group::1.sync.aligned;")
#define TC_COMMIT(mb)      asm volatile("tcgen05.commit.cta_group::1.mbarrier::arrive::one.shared::cluster.b64 [%0];" :: "r"(mb) : "memory")
#define TC_WAIT_LD()       asm volatile("tcgen05.wait::ld.sync.aligned;" ::: "memory")
#define TC_WAIT_ST()       asm volatile("tcgen05.wait::st.sync.aligned;" ::: "memory")
#define TC_FENCE_BEFORE()  asm volatile("tcgen05.fence::before_thread_sync;" ::: "memory")
#define TC_FENCE_AFTER()   asm volatile("tcgen05.fence::after_thread_sync;" ::: "memory")
#define MBAR_INIT(mb, c)   asm volatile("mbarrier.init.shared.b64 [%0], %1;" :: "r"(mb), "r"((uint32_t)(c)) : "memory")
#define CP_ASYNC16(dst, src) asm volatile("cp.async.cg.shared.global [%0], [%1], 16;" :: "r"(dst), "l"(src) : "memory")
#define CP_COMMIT()        asm volatile("cp.async.commit_group;" ::: "memory")
#define CP_WAIT0()         asm volatile("cp.async.wait_group 0;" ::: "memory")
#define FENCE_PROXY()      asm volatile("fence.proxy.async.shared::cta;" ::: "memory")

static __device__ __forceinline__ void mbar_wait(uint32_t mb, uint32_t parity) {
    asm volatile(
        "{\n\t.reg .pred P;\n\t"
        "W%=:\n\tmbarrier.try_wait.parity.acquire.cta.shared::cta.b64 P, [%0], %1, 0x989680;\n\t"
        "@P bra.uni D%=;\n\tbra.uni W%=;\n\tD%=:\n\t}"
        :: "r"(mb), "r"(parity) : "memory");
}

#define LDTM_X16(r, a) \
    asm volatile("tcgen05.ld.sync.aligned.32x32b.x16.b32 " \
        "{%0,%1,%2,%3,%4,%5,%6,%7,%8,%9,%10,%11,%12,%13,%14,%15}, [%16];" \
        : "=r"((r)[0]),"=r"((r)[1]),"=r"((r)[2]),"=r"((r)[3]),"=r"((r)[4]),"=r"((r)[5]),"=r"((r)[6]),"=r"((r)[7]), \
          "=r"((r)[8]),"=r"((r)[9]),"=r"((r)[10]),"=r"((r)[11]),"=r"((r)[12]),"=r"((r)[13]),"=r"((r)[14]),"=r"((r)[15]) \
        : "r"(a))

#define STTM_X8(a, r) \
    asm volatile("tcgen05.st.sync.aligned.32x32b.x8.b32 [%0], " \
        "{%1,%2,%3,%4,%5,%6,%7,%8};" \
        :: "r"(a), \
          "r"((r)[0]),"r"((r)[1]),"r"((r)[2]),"r"((r)[3]),"r"((r)[4]),"r"((r)[5]),"r"((r)[6]),"r"((r)[7]) \
        : "memory")

#define STTM_X16(a, r) \
    asm volatile("tcgen05.st.sync.aligned.32x32b.x16.b32 [%0], " \
        "{%1,%2,%3,%4,%5,%6,%7,%8,%9,%10,%11,%12,%13,%14,%15,%16};" \
        :: "r"(a), \
          "r"((r)[0]),"r"((r)[1]),"r"((r)[2]),"r"((r)[3]),"r"((r)[4]),"r"((r)[5]),"r"((r)[6]),"r"((r)[7]), \
          "r"((r)[8]),"r"((r)[9]),"r"((r)[10]),"r"((r)[11]),"r"((r)[12]),"r"((r)[13]),"r"((r)[14]),"r"((r)[15]) \
        : "memory")

// copy `bytes` from gmem to smem, threads 0-255, 16B units, coalesced
template <int BYTES>
static __device__ __forceinline__ void copy_gang(uint32_t dst, const unsigned char* src, int t) {
    #pragma unroll
    for (int i = 0; i < BYTES / (256 * 16); i++) {
        uint32_t off = (uint32_t)((i * 256 + t) * 16);
        CP_ASYNC16(dst + off, src + off);
    }
}

// GEMM1: S = Q K^T (3 bf16-split passes), K tile in smem buf sbuf
static __device__ __forceinline__ void issue_g1(uint32_t tmem, uint32_t sb, int sbuf) {
    const int DOFF[8] = {0, 2, 4, 6, 1024, 1026, 1028, 1030};
    uint32_t kb_addr = sb + (sbuf ? SM_K1 : SM_K0);
    uint64_t dh = mk_desc(kb_addr);
    uint64_t dl = mk_desc(kb_addr + 32768);
    #pragma unroll
    for (int ks = 0; ks < 8; ks++)
        mma_f16(tmem + T_S, tmem + T_QHI + ks * 8, dh + DOFF[ks], IDESC_N128, ks != 0);
    #pragma unroll
    for (int ks = 0; ks < 8; ks++)
        mma_f16(tmem + T_S, tmem + T_QHI + ks * 8, dl + DOFF[ks], IDESC_N128, 1);
    #pragma unroll
    for (int ks = 0; ks < 8; ks++)
        mma_f16(tmem + T_S, tmem + T_QLO + ks * 8, dh + DOFF[ks], IDESC_N128, 1);
}

// GEMM2: O += P V (V tile in the single smem V buffer)
static __device__ __forceinline__ void issue_g2(uint32_t tmem, uint32_t sb, int first) {
    const int DOFF[8] = {0, 2, 4, 6, 1024, 1026, 1028, 1030};
    uint64_t dh = mk_desc(sb + SM_V);
    uint64_t dl = mk_desc(sb + SM_V + 32768);
    #pragma unroll
    for (int ks = 0; ks < 8; ks++)
        mma_f16(tmem + T_O, tmem + T_PHI + ks * 8, dh + DOFF[ks], IDESC_N128, !(first && ks == 0));
    #pragma unroll
    for (int ks = 0; ks < 8; ks++)
        mma_f16(tmem + T_O, tmem + T_PHI + ks * 8, dl + DOFF[ks], IDESC_N128, 1);
    #pragma unroll
    for (int ks = 0; ks < 8; ks++)
        mma_f16(tmem + T_O, tmem + T_PLO + ks * 8, dh + DOFF[ks], IDESC_N128, 1);
}
#endif  // TC_DEV

__global__ __launch_bounds__(1024, 1)
void attn_tc_kernel(const float* __restrict__ Qg, float* __restrict__ Og) {
#if TC_DEV
    extern __shared__ __align__(1024) char smem[];
    const uint32_t sb = smem_u32(smem);
    const int tid = threadIdx.x;
    const int w = tid >> 5, lane = tid & 31;
    const int sub = w & 3, oct = w >> 2;      // oct = 16-col slice index 0..7
    const int row = sub * 32 + lane;
    const int bh = blockIdx.y;
    const int q0 = blockIdx.x * BM;
    const float* Qp = Qg + ((size_t)bh * SS + q0) * DDIM;
    const unsigned char* blob = g_blob + (size_t)(bh * NKB) * TILE_BYTES;

    if (w == 0) TMEM_ALLOC(sb + SM_TPTR, TMEM_COLS);
    if (tid == 0) { MBAR_INIT(sb + SM_MB1, 1); MBAR_INIT(sb + SM_MB2, 1); }
    __syncthreads();
    uint32_t tmem;
    asm volatile("ld.shared.b32 %0, [%1];" : "=r"(tmem) : "r"(sb + SM_TPTR));

    // per-(thread,iter) mask base: columns oct*16.. within tile j at j*BN
    const uint32_t mbase0 = ((uint32_t)bh << 22) | ((uint32_t)(q0 + row) << 11)
                          | (uint32_t)(oct * 16);

    // ---- prologue: K(0) copy (threads 0-255) + Q -> TMEM (threads 0-127) ----
    if (tid < 256) { copy_gang<65536>(sb + SM_K0, blob + TILE_K, tid); CP_COMMIT(); }
    if (tid < 128) {
        const float* qr = Qp + tid * DDIM;
        uint32_t woff = ((uint32_t)((tid >> 5) & 3)) << 21;
        #pragma unroll
        for (int hb = 0; hb < 4; hb++) {
            uint32_t hi[16], lo[16];
            #pragma unroll
            for (int c4 = 0; c4 < 8; c4++) {
                float4 u = *(const float4*)(qr + hb * 32 + c4 * 4);
                hi[2 * c4]     = prmt_hi(__float_as_uint(u.x), __float_as_uint(u.y));
                hi[2 * c4 + 1] = prmt_hi(__float_as_uint(u.z), __float_as_uint(u.w));
                lo[2 * c4]     = pack_bf2(u.y - trunc_bf(u.y), u.x - trunc_bf(u.x));
                lo[2 * c4 + 1] = pack_bf2(u.w - trunc_bf(u.w), u.z - trunc_bf(u.z));
            }
            STTM_X16(tmem + T_QHI + hb * 16 + woff, hi);
            STTM_X16(tmem + T_QLO + hb * 16 + woff, lo);
        }
        TC_WAIT_ST();
    }
    // mask(0) — overlaps the copy/convert waits
    uint32_t mbits = 0;
    #pragma unroll 4
    for (int t = 0; t < 16; t++)
        mbits |= (tf_word(mbase0 + t) >> 31) << t;
    CP_WAIT0();
    FENCE_PROXY();
    TC_FENCE_BEFORE();
    __syncthreads();
    if (tid == 0) {
        TC_FENCE_AFTER();
        issue_g1(tmem, sb, 0);
        TC_COMMIT(sb + SM_MB1);
    }

    // exp(x/sqrt(128)) == ex2(x * log2(e)/sqrt(128))
    const float scale2 = 0.12752966448211458f;
    float dsum = 0.f;

    for (int j = 0; j < NKB; j++) {
        // A: copy gang — after G2(j-1) done: V(j) -> V buffer, K(j+1) -> other K buf
        if (tid < 256) {
            if (j > 0) mbar_wait(sb + SM_MB2, (j - 1) & 1);
            copy_gang<65536>(sb + SM_V, blob + (size_t)j * TILE_BYTES + TILE_V, tid);
            if (j < NKB - 1)
                copy_gang<65536>(sb + (((j + 1) & 1) ? SM_K1 : SM_K0),
                                 blob + (size_t)(j + 1) * TILE_BYTES + TILE_K, tid);
            CP_COMMIT();
        }
        // B: S ready -> LDTM ISSUE (no wait yet)
        mbar_wait(sb + SM_MB1, j & 1);
        TC_FENCE_AFTER();
        uint32_t sr[16];
        LDTM_X16(sr, tmem + T_S + oct * 16);
        // C: first 4 threefry words of mask(j+1) — covers the TMEM-read drain.
        //    (unconditional/branch-free; value unused on the last iteration)
        const uint32_t nbase = mbase0 + (uint32_t)((j + 1) * BN);
        uint32_t mb_nxt = 0;
        #pragma unroll
        for (int t = 0; t < 4; t++)
            mb_nxt |= (tf_word(nbase + t) >> 31) << t;
        TC_WAIT_LD();
        TC_FENCE_BEFORE();
        // D: copies done + visible to MMA; S tile drained
        CP_WAIT0();
        FENCE_PROXY();
        __syncthreads();
        // E: launch next GEMM1 into freed S
        if (tid == 0 && j < NKB - 1) {
            TC_FENCE_AFTER();
            issue_g1(tmem, sb, (j + 1) & 1);
            TC_COMMIT(sb + SM_MB1);
        }
        // F: exp + mask(j) + bf16 split -> P, INTERLEAVED (same basic block,
        //    no volatile in between) with the remaining 12 threefry words of
        //    mask(j+1): alu-pipe threefry fills MUFU/fma latency slots.
        uint32_t phi[8], plo[8];
        #pragma unroll
        for (int t2 = 0; t2 < 8; t2++) {
            float e0 = ex2f(__uint_as_float(sr[2 * t2]) * scale2);
            float e1 = ex2f(__uint_as_float(sr[2 * t2 + 1]) * scale2);
            dsum += e0 + e1;
            float p0 = (mbits & (1u << (2 * t2)))     ? 0.f : e0;
            float p1 = (mbits & (1u << (2 * t2 + 1))) ? 0.f : e1;
            phi[t2] = prmt_hi(__float_as_uint(p0), __float_as_uint(p1));
            plo[t2] = pack_bf2(p1 - trunc_bf(p1), p0 - trunc_bf(p0));
        }
        #pragma unroll 4
        for (int t = 4; t < 16; t++)
            mb_nxt |= (tf_word(nbase + t) >> 31) << t;
        mbits = mb_nxt;
        uint32_t woff = ((uint32_t)sub) << 21;
        STTM_X8(tmem + T_PHI + oct * 8 + woff, phi);
        STTM_X8(tmem + T_PLO + oct * 8 + woff, plo);
        TC_WAIT_ST();
        TC_FENCE_BEFORE();
        __syncthreads();
        // G: launch GEMM2
        if (tid == 0) {
            TC_FENCE_AFTER();
            issue_g2(tmem, sb, j == 0);
            TC_COMMIT(sb + SM_MB2);
        }
    }

    mbar_wait(sb + SM_MB2, (NKB - 1) & 1);
    TC_FENCE_AFTER();

    // denominator reduce across the 8 column slices
    ((float*)(smem + SM_DSUM))[row * 8 + oct] = dsum;
    __syncthreads();
    float tot = 0.f;
    #pragma unroll
    for (int i = 0; i < 8; i++)
        tot += ((float*)(smem + SM_DSUM))[row * 8 + i];
    float rs = 2.0f / tot;   // dropout 1/(1-p)=2 folded in

    uint32_t orv[16];
    LDTM_X16(orv, tmem + T_O + oct * 16);
    TC_WAIT_LD();
    TC_FENCE_BEFORE();
    size_t orow = ((size_t)bh * SS + (size_t)(q0 + row)) * DDIM;
    #pragma unroll
    for (int t = 0; t < 16; t++)
        Og[orow + oct * 16 + t] = __uint_as_float(orv[t]) * rs;

    __syncthreads();
    if (w == 0) { TMEM_RELINQ(); TMEM_DEALLOC(tmem, TMEM_COLS); }
#else
    (void)Qg; (void)Og;
#endif
}

// ===========================================================================
// host dispatch
// ===========================================================================
extern "C" void kernel_launch(void* const* d_in, const int* in_sizes, int n_in,
                              void* d_out, int out_size) {
    (void)in_sizes; (void)n_in; (void)out_size;
    const float* Q = (const float*)d_in[0];
    const float* K = (const float*)d_in[1];
    const float* V = (const float*)d_in[2];
    float* O = (float*)d_out;

    cudaFuncAttributes fa;
    bool tc_ok = (cudaFuncGetAttributes(&fa, attn_tc_kernel) == cudaSuccess)
               && fa.numRegs > 40;

    if (tc_ok) {
        cudaFuncSetAttribute(prep_kv_kernel,
                             cudaFuncAttributeMaxDynamicSharedMemorySize, 65536);
        prep_kv_kernel<<<512, 256, 65536>>>(K, V);
        cudaFuncSetAttribute(attn_tc_kernel,
                             cudaFuncAttributeMaxDynamicSharedMemorySize, TC_SMEM);
        dim3 grid(SS / BM, 32);
        attn_tc_kernel<<<grid, 1024, TC_SMEM>>>(Q, O);
    } else {
        cudaFuncSetAttribute(attn_dropout_kernel,
                             cudaFuncAttributeMaxDynamicSharedMemorySize, FB_SMEM);
        dim3 grid(SS / FBM, 32);
        attn_dropout_kernel<<<grid, NT, FB_SMEM>>>(Q, K, V, O);
    }
}

// round 16
// speedup vs baseline: 1.0357x; 1.0357x over previous
#include <cuda_runtime.h>
#include <stdint.h>

#define SS 2048
#define DDIM 128
#define NT 256

// ===========================================================================
// threefry-2x32, key=(0,42); jax_threefry_partitionable semantics:
// word(i) = hi ^ lo of threefry2x32(key, ctr=(0, i)); keep iff MSB==0.
// ===========================================================================
static __device__ __forceinline__ uint32_t tf_word(uint32_t idx) {
    const uint32_t K0 = 0u, K1 = 42u, K2 = 0x1BD11BDAu ^ 42u;
    uint32_t x0 = 0u + K0, x1 = idx + K1;
#define TFR(R) { x0 += x1; x1 = __funnelshift_l(x1, x1, (R)); x1 ^= x0; }
    TFR(13) TFR(15) TFR(26) TFR(6)
    x0 += K1; x1 += K2 + 1u;
    TFR(17) TFR(29) TFR(16) TFR(24)
    x0 += K2; x1 += K0 + 2u;
    TFR(13) TFR(15) TFR(26) TFR(6)
    x0 += K0; x1 += K1 + 3u;
    TFR(17) TFR(29) TFR(16) TFR(24)
    x0 += K1; x1 += K2 + 4u;
    TFR(13) TFR(15) TFR(26) TFR(6)
    x0 += K2; x1 += K0 + 5u;
#undef TFR
    return x0 ^ x1;
}

// ===========================================================================
// Fallback SIMT kernel (R2, passed at 2073 us)
// ===========================================================================
#define FBM 64
#define FBN 64
#define SQS 132
#define SPS 68

__global__ __launch_bounds__(NT, 2)
void attn_dropout_kernel(const float* __restrict__ Qg,
                         const float* __restrict__ Kg,
                         const float* __restrict__ Vg,
                         float* __restrict__ Og) {
    extern __shared__ float fsm[];
    float* sQ = fsm;
    float* sK = fsm + FBM * SQS;
    float* sV = fsm + 2 * FBM * SQS;
    float* sP = sK;

    const int tid = threadIdx.x;
    const int tx = tid & 15;
    const int ty = tid >> 4;
    const int bh = blockIdx.y;
    const int q0 = blockIdx.x * FBM;

    const float* Qp = Qg + ((size_t)bh * SS + q0) * DDIM;
    const float* Kp = Kg + (size_t)bh * SS * DDIM;
    const float* Vp = Vg + (size_t)bh * SS * DDIM;

    #pragma unroll
    for (int it = 0; it < (FBM * DDIM) / (4 * NT); it++) {
        int e = (tid + it * NT) * 4;
        int r = e >> 7, c = e & 127;
        *(float4*)(sQ + r * SQS + c) = *(const float4*)(Qp + e);
    }

    float acc[4][8];
    #pragma unroll
    for (int j = 0; j < 4; j++)
        #pragma unroll
        for (int i = 0; i < 8; i++) acc[j][i] = 0.f;
    float dsum[4] = {0.f, 0.f, 0.f, 0.f};
    const float scale = 0.08838834764831845f;

    for (int kb = 0; kb < SS / FBN; kb++) {
        __syncthreads();
        const float* Kb = Kp + (size_t)kb * FBN * DDIM;
        const float* Vb = Vp + (size_t)kb * FBN * DDIM;
        #pragma unroll
        for (int it = 0; it < (FBN * DDIM) / (4 * NT); it++) {
            int e = (tid + it * NT) * 4;
            int r = e >> 7, c = e & 127;
            *(float4*)(sK + r * SQS + c) = *(const float4*)(Kb + e);
            *(float4*)(sV + r * DDIM + c) = *(const float4*)(Vb + e);
        }
        __syncthreads();

        float sacc[4][4];
        #pragma unroll
        for (int j = 0; j < 4; j++)
            #pragma unroll
            for (int i = 0; i < 4; i++) sacc[j][i] = 0.f;

        #pragma unroll 4
        for (int d0 = 0; d0 < DDIM; d0 += 4) {
            float4 aq[4], bk[4];
            #pragma unroll
            for (int j = 0; j < 4; j++)
                aq[j] = *(const float4*)(sQ + (4 * ty + j) * SQS + d0);
            #pragma unroll
            for (int i = 0; i < 4; i++)
                bk[i] = *(const float4*)(sK + (tx + 16 * i) * SQS + d0);
            #pragma unroll
            for (int j = 0; j < 4; j++)
                #pragma unroll
                for (int i = 0; i < 4; i++)
                    sacc[j][i] += aq[j].x * bk[i].x + aq[j].y * bk[i].y
                                + aq[j].z * bk[i].z + aq[j].w * bk[i].w;
        }
        __syncthreads();

        uint32_t baseIdx = ((uint32_t)bh << 22) | ((uint32_t)q0 << 11)
                         | (uint32_t)(kb * FBN);
        #pragma unroll
        for (int j = 0; j < 4; j++) {
            #pragma unroll
            for (int i = 0; i < 4; i++) {
                float ex = __expf(sacc[j][i] * scale);
                dsum[j] += ex;
                uint32_t idx = baseIdx + ((uint32_t)(4 * ty + j) << 11)
                             + (uint32_t)(tx + 16 * i);
                uint32_t w = tf_word(idx);
                sP[(4 * ty + j) * SPS + (tx + 16 * i)] = (w & 0x80000000u) ? 0.f : ex;
            }
        }
        __syncthreads();

        #pragma unroll 2
        for (int c0 = 0; c0 < FBN; c0 += 4) {
            float4 p4[4];
            #pragma unroll
            for (int j = 0; j < 4; j++)
                p4[j] = *(const float4*)(sP + (4 * ty + j) * SPS + c0);
            #pragma unroll
            for (int cc = 0; cc < 4; cc++) {
                float bb[8];
                #pragma unroll
                for (int i = 0; i < 8; i++)
                    bb[i] = sV[(c0 + cc) * DDIM + tx + 16 * i];
                #pragma unroll
                for (int j = 0; j < 4; j++) {
                    float pj = ((const float*)&p4[j])[cc];
                    #pragma unroll
                    for (int i = 0; i < 8; i++)
                        acc[j][i] += pj * bb[i];
                }
            }
        }
    }

    __syncthreads();
    #pragma unroll
    for (int j = 0; j < 4; j++)
        sP[(4 * ty + j) * SPS + tx] = dsum[j];
    __syncthreads();

    #pragma unroll
    for (int j = 0; j < 4; j++) {
        float s = 0.f;
        #pragma unroll
        for (int t = 0; t < 16; t++) s += sP[(4 * ty + j) * SPS + t];
        float rs = 2.0f / s;
        size_t orow = ((size_t)bh * SS + (size_t)(q0 + 4 * ty + j)) * DDIM;
        #pragma unroll
        for (int i = 0; i < 8; i++)
            Og[orow + tx + 16 * i] = acc[j][i] * rs;
    }
}

#define FB_SMEM ((2 * FBM * SQS + FBN * DDIM) * 4)

// ===========================================================================
// common helpers
// ===========================================================================
#define BM 128
#define BN 128
#define NKB (SS / BN)            /* 16 kv tiles */

static __device__ __forceinline__ uint32_t smem_u32(const void* p) {
    uint32_t a;
    asm("{ .reg .u64 t; cvta.to.shared.u64 t, %1; cvt.u32.u64 %0, t; }" : "=r"(a) : "l"(p));
    return a;
}
static __device__ __forceinline__ uint32_t swz(uint32_t o) { return o ^ ((o >> 3) & 0x70u); }
// blocked SW128 K-major layout, nrows=128: atom = 8 rows x 64 bf16 (1024B)
static __device__ __forceinline__ uint32_t koff(int n, int k) {
    return ((uint32_t)((n >> 3) + ((k >> 6) << 4)) << 10)
         + (((uint32_t)n & 7u) << 7) + (((uint32_t)k & 63u) << 1);
}
static __device__ __forceinline__ uint32_t prmt_hi(uint32_t a, uint32_t b) {
    uint32_t r; asm("prmt.b32 %0,%1,%2,0x7632;" : "=r"(r) : "r"(a), "r"(b)); return r;
}
static __device__ __forceinline__ float trunc_bf(float x) {
    return __uint_as_float(__float_as_uint(x) & 0xffff0000u);
}
static __device__ __forceinline__ uint32_t pack_bf2(float hi_elem, float lo_elem) {
    uint32_t r; asm("cvt.rn.bf16x2.f32 %0,%1,%2;" : "=r"(r) : "f"(hi_elem), "f"(lo_elem)); return r;
}
static __device__ __forceinline__ float ex2f(float x) {
    float r; asm("ex2.approx.f32 %0, %1;" : "=f"(r) : "f"(x)); return r;
}

// blob tile layout (128KB per tile): KHI 32K | KLO 32K | VHI 32K | VLO 32K
#define TILE_BYTES 131072
#define TILE_K 0
#define TILE_V 65536

// main-kernel smem map
#define SM_K0   0               /* KHI0 | KLO0, 64KB */
#define SM_K1   65536           /* KHI1 | KLO1, 64KB */
#define SM_V    131072          /* VHI | VLO, 64KB */
#define SM_DSUM 196608          /* 128 rows x 8 octs x 4B = 4096 */
#define SM_TPTR 200704
#define SM_MB1  200712
#define SM_MB2  200720
#define TC_SMEM 200768

// pre-converted bf16 hi/lo K/V tiles: 32 bh x 16 tiles x 128KB = 64 MiB
__device__ __align__(1024) unsigned char g_blob[32 * 16 * TILE_BYTES];

// ===========================================================================
// pre-kernel: fp32 K/V -> bf16 hi/lo 128-row tile blobs, MMA-swizzled
// ===========================================================================
__global__ __launch_bounds__(256)
void prep_kv_kernel(const float* __restrict__ Kg, const float* __restrict__ Vg) {
    extern __shared__ __align__(16) unsigned char vs[];   // 64KB: VHI | VLO staged
    const int tile = blockIdx.x;            // bh*16 + kb
    const int bh = tile >> 4, kb = tile & 15;
    const int tid = threadIdx.x;
    const float* Kb = Kg + ((size_t)bh * SS + (size_t)kb * BN) * DDIM;
    const float* Vb = Vg + ((size_t)bh * SS + (size_t)kb * BN) * DDIM;
    unsigned char* out = g_blob + (size_t)tile * TILE_BYTES;

    #pragma unroll
    for (int it = 0; it < 16; it++) {
        int idx = it * 256 + tid;           // float4 index, 4096 total
        int n = idx >> 5, k = (idx & 31) * 4;
        float4 u = *(const float4*)(Kb + n * DDIM + k);
        uint32_t h0 = prmt_hi(__float_as_uint(u.x), __float_as_uint(u.y));
        uint32_t h1 = prmt_hi(__float_as_uint(u.z), __float_as_uint(u.w));
        uint32_t l0 = pack_bf2(u.y - trunc_bf(u.y), u.x - trunc_bf(u.x));
        uint32_t l1 = pack_bf2(u.w - trunc_bf(u.w), u.z - trunc_bf(u.z));
        uint32_t o = swz(koff(n, k));
        *(uint2*)(out + TILE_K + o)         = make_uint2(h0, h1);
        *(uint2*)(out + TILE_K + 32768 + o) = make_uint2(l0, l1);
    }
    int w = tid >> 5, lid = tid & 31;
    #pragma unroll
    for (int i = 0; i < 8; i++) {
        int p = w * 8 + i;                  // kv pair 0..63
        #pragma unroll
        for (int j = 0; j < 4; j++) {
            int d = lid + 32 * j;
            float f0 = Vb[(2 * p) * DDIM + d];
            float f1 = Vb[(2 * p + 1) * DDIM + d];
            uint32_t hw = prmt_hi(__float_as_uint(f0), __float_as_uint(f1));
            uint32_t lw = pack_bf2(f1 - trunc_bf(f1), f0 - trunc_bf(f0));
            uint32_t o = swz(koff(d, 2 * p));
            *(uint32_t*)(vs + o) = hw;
            *(uint32_t*)(vs + 32768 + o) = lw;
        }
    }
    __syncthreads();
    #pragma unroll
    for (int i = 0; i < 16; i++) {
        int e = (i * 256 + tid) * 16;
        *(float4*)(out + TILE_V + e) = *(const float4*)(vs + e);
    }
}

// ===========================================================================
// tcgen05 kernel — only real on the sm_103a pass
// ===========================================================================
#if !defined(__CUDA_ARCH__) || defined(__CUDA_ARCH_FEAT_SM103_ALL) || \
    (defined(__CUDA_ARCH_SPECIFIC__) && (__CUDA_ARCH_SPECIFIC__ >= 1000))
#define TC_PATH_COMPILED 1
#else
#define TC_PATH_COMPILED 0
#endif
#if defined(__CUDA_ARCH__) && TC_PATH_COMPILED
#define TC_DEV 1
#else
#define TC_DEV 0
#endif

// TMEM map: QHI 0, QLO 64, S 128 (128 cols), PHI 256, PLO 320, O 384 (128 cols)
#define T_QHI 0
#define T_QLO 64
#define T_S   128
#define T_PHI 256
#define T_PLO 320
#define T_O   384
#define TMEM_COLS 512

#define IDESC_N128 0x8200490u   /* kind::f16, bf16 x bf16 -> f32, M=128, N=128 */

static constexpr uint64_t DESC_BASE =
    (uint64_t(2) << 61) | (uint64_t(1) << 46) | (uint64_t(64) << 32) | (uint64_t(1) << 16);
static __device__ __forceinline__ uint64_t mk_desc(uint32_t addr) {
    return DESC_BASE | ((uint64_t)(addr >> 4) & 0x3FFFull);
}

#if TC_DEV
static __device__ __forceinline__ void mma_f16(uint32_t d, uint32_t a, uint64_t bdesc,
                                               uint32_t idesc, int acc) {
    asm volatile(
        "{\n\t.reg .pred p;\n\tsetp.ne.u32 p,%5,0;\n\t"
        "tcgen05.mma.cta_group::1.kind::f16 [%0],[%1],%2,%3,{%4,%4,%4,%4},p;\n\t}"
        :: "r"(d), "r"(a), "l"(bdesc), "r"(idesc), "r"(0u), "r"((uint32_t)acc) : "memory");
}

#define TMEM_ALLOC(sa, n)  asm volatile("tcgen05.alloc.cta_group::1.sync.aligned.shared::cta.b32 [%0], %1;" :: "r"(sa), "r"((uint32_t)(n)) : "memory")
#define TMEM_DEALLOC(t, n) asm volatile("tcgen05.dealloc.cta_group::1.sync.aligned.b32 %0, %1;" :: "r"(t), "r"((uint32_t)(n)))
#define TMEM_RELINQ()      asm volatile("tcgen05.relinquish_alloc_permit.cta_group::1.sync.aligned;")
#define TC_COMMIT(mb)      asm volatile("tcgen05.commit.cta_group::1.mbarrier::arrive::one.shared::cluster.b64 [%0];" :: "r"(mb) : "memory")
#define TC_WAIT_LD()       asm volatile("tcgen05.wait::ld.sync.aligned;" ::: "memory")
#define TC_WAIT_ST()       asm volatile("tcgen05.wait::st.sync.aligned;" ::: "memory")
#define TC_FENCE_BEFORE()  asm volatile("tcgen05.fence::before_thread_sync;" ::: "memory")
#define TC_FENCE_AFTER()   asm volatile("tcgen05.fence::after_thread_sync;" ::: "memory")
#define MBAR_INIT(mb, c)   asm volatile("mbarrier.init.shared.b64 [%0], %1;" :: "r"(mb), "r"((uint32_t)(c)) : "memory")
#define CP_ASYNC16(dst, src) asm volatile("cp.async.cg.shared.global [%0], [%1], 16;" :: "r"(dst), "l"(src) : "memory")
#define CP_COMMIT()        asm volatile("cp.async.commit_group;" ::: "memory")
#define CP_WAIT0()         asm volatile("cp.async.wait_group 0;" ::: "memory")
#define FENCE_PROXY()      asm volatile("fence.proxy.async.shared::cta;" ::: "memory")

static __device__ __forceinline__ void mbar_wait(uint32_t mb, uint32_t parity) {
    asm volatile(
        "{\n\t.reg .pred P;\n\t"
        "W%=:\n\tmbarrier.try_wait.parity.acquire.cta.shared::cta.b64 P, [%0], %1, 0x989680;\n\t"
        "@P bra.uni D%=;\n\tbra.uni W%=;\n\tD%=:\n\t}"
        :: "r"(mb), "r"(parity) : "memory");
}

#define LDTM_X16(r, a) \
    asm volatile("tcgen05.ld.sync.aligned.32x32b.x16.b32 " \
        "{%0,%1,%2,%3,%4,%5,%6,%7,%8,%9,%10,%11,%12,%13,%14,%15}, [%16];" \
        : "=r"((r)[0]),"=r"((r)[1]),"=r"((r)[2]),"=r"((r)[3]),"=r"((r)[4]),"=r"((r)[5]),"=r"((r)[6]),"=r"((r)[7]), \
          "=r"((r)[8]),"=r"((r)[9]),"=r"((r)[10]),"=r"((r)[11]),"=r"((r)[12]),"=r"((r)[13]),"=r"((r)[14]),"=r"((r)[15]) \
        : "r"(a))

#define STTM_X8(a, r) \
    asm volatile("tcgen05.st.sync.aligned.32x32b.x8.b32 [%0], " \
        "{%1,%2,%3,%4,%5,%6,%7,%8};" \
        :: "r"(a), \
          "r"((r)[0]),"r"((r)[1]),"r"((r)[2]),"r"((r)[3]),"r"((r)[4]),"r"((r)[5]),"r"((r)[6]),"r"((r)[7]) \
        : "memory")

#define STTM_X16(a, r) \
    asm volatile("tcgen05.st.sync.aligned.32x32b.x16.b32 [%0], " \
        "{%1,%2,%3,%4,%5,%6,%7,%8,%9,%10,%11,%12,%13,%14,%15,%16};" \
        :: "r"(a), \
          "r"((r)[0]),"r"((r)[1]),"r"((r)[2]),"r"((r)[3]),"r"((r)[4]),"r"((r)[5]),"r"((r)[6]),"r"((r)[7]), \
          "r"((r)[8]),"r"((r)[9]),"r"((r)[10]),"r"((r)[11]),"r"((r)[12]),"r"((r)[13]),"r"((r)[14]),"r"((r)[15]) \
        : "memory")

// copy `bytes` from gmem to smem, threads 0-255, 16B units, coalesced
template <int BYTES>
static __device__ __forceinline__ void copy_gang(uint32_t dst, const unsigned char* src, int t) {
    #pragma unroll
    for (int i = 0; i < BYTES / (256 * 16); i++) {
        uint32_t off = (uint32_t)((i * 256 + t) * 16);
        CP_ASYNC16(dst + off, src + off);
    }
}

// mask bits for 16 consecutive kv columns starting at index `base`
static __device__ __forceinline__ uint32_t mask16(uint32_t base) {
    uint32_t m = 0;
    #pragma unroll 4
    for (int t = 0; t < 16; t++)
        m |= (tf_word(base + t) >> 31) << t;
    return m;
}

// GEMM1: S = Q K^T (3 bf16-split passes), K tile in smem buf sbuf
static __device__ __forceinline__ void issue_g1(uint32_t tmem, uint32_t sb, int sbuf) {
    const int DOFF[8] = {0, 2, 4, 6, 1024, 1026, 1028, 1030};
    uint32_t kb_addr = sb + (sbuf ? SM_K1 : SM_K0);
    uint64_t dh = mk_desc(kb_addr);
    uint64_t dl = mk_desc(kb_addr + 32768);
    #pragma unroll
    for (int ks = 0; ks < 8; ks++)
        mma_f16(tmem + T_S, tmem + T_QHI + ks * 8, dh + DOFF[ks], IDESC_N128, ks != 0);
    #pragma unroll
    for (int ks = 0; ks < 8; ks++)
        mma_f16(tmem + T_S, tmem + T_QHI + ks * 8, dl + DOFF[ks], IDESC_N128, 1);
    #pragma unroll
    for (int ks = 0; ks < 8; ks++)
        mma_f16(tmem + T_S, tmem + T_QLO + ks * 8, dh + DOFF[ks], IDESC_N128, 1);
}

// GEMM2: O += P V (V tile in the single smem V buffer)
static __device__ __forceinline__ void issue_g2(uint32_t tmem, uint32_t sb, int first) {
    const int DOFF[8] = {0, 2, 4, 6, 1024, 1026, 1028, 1030};
    uint64_t dh = mk_desc(sb + SM_V);
    uint64_t dl = mk_desc(sb + SM_V + 32768);
    #pragma unroll
    for (int ks = 0; ks < 8; ks++)
        mma_f16(tmem + T_O, tmem + T_PHI + ks * 8, dh + DOFF[ks], IDESC_N128, !(first && ks == 0));
    #pragma unroll
    for (int ks = 0; ks < 8; ks++)
        mma_f16(tmem + T_O, tmem + T_PHI + ks * 8, dl + DOFF[ks], IDESC_N128, 1);
    #pragma unroll
    for (int ks = 0; ks < 8; ks++)
        mma_f16(tmem + T_O, tmem + T_PLO + ks * 8, dh + DOFF[ks], IDESC_N128, 1);
}
#endif  // TC_DEV

__global__ __launch_bounds__(1024, 1)
void attn_tc_kernel(const float* __restrict__ Qg, float* __restrict__ Og) {
#if TC_DEV
    extern __shared__ __align__(1024) char smem[];
    const uint32_t sb = smem_u32(smem);
    const int tid = threadIdx.x;
    const int w = tid >> 5, lane = tid & 31;
    const int sub = w & 3, oct = w >> 2;      // oct = 16-col slice index 0..7
    const int row = sub * 32 + lane;
    const int bh = blockIdx.y;
    const int q0 = blockIdx.x * BM;
    const float* Qp = Qg + ((size_t)bh * SS + q0) * DDIM;
    const unsigned char* blob = g_blob + (size_t)(bh * NKB) * TILE_BYTES;

    if (w == 0) TMEM_ALLOC(sb + SM_TPTR, TMEM_COLS);
    if (tid == 0) { MBAR_INIT(sb + SM_MB1, 1); MBAR_INIT(sb + SM_MB2, 1); }
    __syncthreads();
    uint32_t tmem;
    asm volatile("ld.shared.b32 %0, [%1];" : "=r"(tmem) : "r"(sb + SM_TPTR));

    // per-(thread,iter) mask base: columns oct*16.. within tile j at j*BN
    const uint32_t mbase0 = ((uint32_t)bh << 22) | ((uint32_t)(q0 + row) << 11)
                          | (uint32_t)(oct * 16);

    // ---- prologue: K(0) copy (threads 0-255) + Q -> TMEM (threads 0-127) ----
    if (tid < 256) { copy_gang<65536>(sb + SM_K0, blob + TILE_K, tid); CP_COMMIT(); }
    if (tid < 128) {
        const float* qr = Qp + tid * DDIM;
        uint32_t woff = ((uint32_t)((tid >> 5) & 3)) << 21;
        #pragma unroll
        for (int hb = 0; hb < 4; hb++) {
            uint32_t hi[16], lo[16];
            #pragma unroll
            for (int c4 = 0; c4 < 8; c4++) {
                float4 u = *(const float4*)(qr + hb * 32 + c4 * 4);
                hi[2 * c4]     = prmt_hi(__float_as_uint(u.x), __float_as_uint(u.y));
                hi[2 * c4 + 1] = prmt_hi(__float_as_uint(u.z), __float_as_uint(u.w));
                lo[2 * c4]     = pack_bf2(u.y - trunc_bf(u.y), u.x - trunc_bf(u.x));
                lo[2 * c4 + 1] = pack_bf2(u.w - trunc_bf(u.w), u.z - trunc_bf(u.z));
            }
            STTM_X16(tmem + T_QHI + hb * 16 + woff, hi);
            STTM_X16(tmem + T_QLO + hb * 16 + woff, lo);
        }
        TC_WAIT_ST();
    }
    // mask(0) — overlaps the copy/convert waits
    uint32_t mbits = mask16(mbase0);
    CP_WAIT0();
    FENCE_PROXY();
    TC_FENCE_BEFORE();
    __syncthreads();
    if (tid == 0) {
        TC_FENCE_AFTER();
        issue_g1(tmem, sb, 0);
        TC_COMMIT(sb + SM_MB1);
    }

    // exp(x/sqrt(128)) == ex2(x * log2(e)/sqrt(128))
    const float scale2 = 0.12752966448211458f;
    float dsum0 = 0.f, dsum1 = 0.f;   // two chains: halve the serial FADD depth

    #pragma unroll 2
    for (int j = 0; j < NKB; j++) {
        // A: copy gang — after G2(j-1) done: V(j) -> V buffer, K(j+1) -> other K buf
        if (tid < 256) {
            if (j > 0) mbar_wait(sb + SM_MB2, (j - 1) & 1);
            copy_gang<65536>(sb + SM_V, blob + (size_t)j * TILE_BYTES + TILE_V, tid);
            if (j < NKB - 1)
                copy_gang<65536>(sb + (((j + 1) & 1) ? SM_K1 : SM_K0),
                                 blob + (size_t)(j + 1) * TILE_BYTES + TILE_K, tid);
            CP_COMMIT();
        }
        // B: S ready -> LDTM ISSUE (no wait yet)
        mbar_wait(sb + SM_MB1, j & 1);
        TC_FENCE_AFTER();
        uint32_t sr[16];
        LDTM_X16(sr, tmem + T_S + oct * 16);
        // C: threefry mask for iteration j+1 — fills the TMEM-read drain
        uint32_t mb_nxt = 0;
        if (j < NKB - 1)
            mb_nxt = mask16(mbase0 + (uint32_t)((j + 1) * BN));
        TC_WAIT_LD();
        TC_FENCE_BEFORE();
        // D: copies done + visible to MMA; S tile drained
        CP_WAIT0();
        FENCE_PROXY();
        __syncthreads();
        // E: launch next GEMM1 into freed S
        if (tid == 0 && j < NKB - 1) {
            TC_FENCE_AFTER();
            issue_g1(tmem, sb, (j + 1) & 1);
            TC_COMMIT(sb + SM_MB1);
        }
        // F: exp + mask(j) + bf16 split -> P
        uint32_t phi[8], plo[8];
        #pragma unroll
        for (int t2 = 0; t2 < 8; t2++) {
            float e0 = ex2f(__uint_as_float(sr[2 * t2]) * scale2);
            float e1 = ex2f(__uint_as_float(sr[2 * t2 + 1]) * scale2);
            dsum0 += e0;
            dsum1 += e1;
            float p0 = (mbits & (1u << (2 * t2)))     ? 0.f : e0;
            float p1 = (mbits & (1u << (2 * t2 + 1))) ? 0.f : e1;
            phi[t2] = prmt_hi(__float_as_uint(p0), __float_as_uint(p1));
            plo[t2] = pack_bf2(p1 - trunc_bf(p1), p0 - trunc_bf(p0));
        }
        mbits = mb_nxt;
        uint32_t woff = ((uint32_t)sub) << 21;
        STTM_X8(tmem + T_PHI + oct * 8 + woff, phi);
        STTM_X8(tmem + T_PLO + oct * 8 + woff, plo);
        TC_WAIT_ST();
        TC_FENCE_BEFORE();
        __syncthreads();
        // G: launch GEMM2
        if (tid == 0) {
            TC_FENCE_AFTER();
            issue_g2(tmem, sb, j == 0);
            TC_COMMIT(sb + SM_MB2);
        }
    }

    mbar_wait(sb + SM_MB2, (NKB - 1) & 1);
    TC_FENCE_AFTER();

    // denominator reduce across the 8 column slices
    ((float*)(smem + SM_DSUM))[row * 8 + oct] = dsum0 + dsum1;
    __syncthreads();
    float tot = 0.f;
    #pragma unroll
    for (int i = 0; i < 8; i++)
        tot += ((float*)(smem + SM_DSUM))[row * 8 + i];
    float rs = 2.0f / tot;   // dropout 1/(1-p)=2 folded in

    uint32_t orv[16];
    LDTM_X16(orv, tmem + T_O + oct * 16);
    TC_WAIT_LD();
    TC_FENCE_BEFORE();
    size_t orow = ((size_t)bh * SS + (size_t)(q0 + row)) * DDIM;
    #pragma unroll
    for (int t = 0; t < 16; t++)
        Og[orow + oct * 16 + t] = __uint_as_float(orv[t]) * rs;

    __syncthreads();
    if (w == 0) { TMEM_RELINQ(); TMEM_DEALLOC(tmem, TMEM_COLS); }
#else
    (void)Qg; (void)Og;
#endif
}

// ===========================================================================
// host dispatch
// ===========================================================================
extern "C" void kernel_launch(void* const* d_in, const int* in_sizes, int n_in,
                              void* d_out, int out_size) {
    (void)in_sizes; (void)n_in; (void)out_size;
    const float* Q = (const float*)d_in[0];
    const float* K = (const float*)d_in[1];
    const float* V = (const float*)d_in[2];
    float* O = (float*)d_out;

    cudaFuncAttributes fa;
    bool tc_ok = (cudaFuncGetAttributes(&fa, attn_tc_kernel) == cudaSuccess)
               && fa.numRegs > 40;

    if (tc_ok) {
        cudaFuncSetAttribute(prep_kv_kernel,
                             cudaFuncAttributeMaxDynamicSharedMemorySize, 65536);
        prep_kv_kernel<<<512, 256, 65536>>>(K, V);
        cudaFuncSetAttribute(attn_tc_kernel,
                             cudaFuncAttributeMaxDynamicSharedMemorySize, TC_SMEM);
        dim3 grid(SS / BM, 32);
        attn_tc_kernel<<<grid, 1024, TC_SMEM>>>(Q, O);
    } else {
        cudaFuncSetAttribute(attn_dropout_kernel,
                             cudaFuncAttributeMaxDynamicSharedMemorySize, FB_SMEM);
        dim3 grid(SS / FBM, 32);
        attn_dropout_kernel<<<grid, NT, FB_SMEM>>>(Q, K, V, O);
    }
}

// round 17
// speedup vs baseline: 1.0972x; 1.0594x over previous
#include <cuda_runtime.h>
#include <stdint.h>

#define SS 2048
#define DDIM 128
#define NT 256

// ===========================================================================
// threefry-2x32, key=(0,42); jax_threefry_partitionable semantics:
// word(i) = hi ^ lo of threefry2x32(key, ctr=(0, i)); keep iff MSB==0.
// ===========================================================================
static __device__ __forceinline__ uint32_t tf_word(uint32_t idx) {
    const uint32_t K0 = 0u, K1 = 42u, K2 = 0x1BD11BDAu ^ 42u;
    uint32_t x0 = 0u + K0, x1 = idx + K1;
#define TFR(R) { x0 += x1; x1 = __funnelshift_l(x1, x1, (R)); x1 ^= x0; }
    TFR(13) TFR(15) TFR(26) TFR(6)
    x0 += K1; x1 += K2 + 1u;
    TFR(17) TFR(29) TFR(16) TFR(24)
    x0 += K2; x1 += K0 + 2u;
    TFR(13) TFR(15) TFR(26) TFR(6)
    x0 += K0; x1 += K1 + 3u;
    TFR(17) TFR(29) TFR(16) TFR(24)
    x0 += K1; x1 += K2 + 4u;
    TFR(13) TFR(15) TFR(26) TFR(6)
    x0 += K2; x1 += K0 + 5u;
#undef TFR
    return x0 ^ x1;
}

// ===========================================================================
// Fallback SIMT kernel (R2, passed at 2073 us)
// ===========================================================================
#define FBM 64
#define FBN 64
#define SQS 132
#define SPS 68

__global__ __launch_bounds__(NT, 2)
void attn_dropout_kernel(const float* __restrict__ Qg,
                         const float* __restrict__ Kg,
                         const float* __restrict__ Vg,
                         float* __restrict__ Og) {
    extern __shared__ float fsm[];
    float* sQ = fsm;
    float* sK = fsm + FBM * SQS;
    float* sV = fsm + 2 * FBM * SQS;
    float* sP = sK;

    const int tid = threadIdx.x;
    const int tx = tid & 15;
    const int ty = tid >> 4;
    const int bh = blockIdx.y;
    const int q0 = blockIdx.x * FBM;

    const float* Qp = Qg + ((size_t)bh * SS + q0) * DDIM;
    const float* Kp = Kg + (size_t)bh * SS * DDIM;
    const float* Vp = Vg + (size_t)bh * SS * DDIM;

    #pragma unroll
    for (int it = 0; it < (FBM * DDIM) / (4 * NT); it++) {
        int e = (tid + it * NT) * 4;
        int r = e >> 7, c = e & 127;
        *(float4*)(sQ + r * SQS + c) = *(const float4*)(Qp + e);
    }

    float acc[4][8];
    #pragma unroll
    for (int j = 0; j < 4; j++)
        #pragma unroll
        for (int i = 0; i < 8; i++) acc[j][i] = 0.f;
    float dsum[4] = {0.f, 0.f, 0.f, 0.f};
    const float scale = 0.08838834764831845f;

    for (int kb = 0; kb < SS / FBN; kb++) {
        __syncthreads();
        const float* Kb = Kp + (size_t)kb * FBN * DDIM;
        const float* Vb = Vp + (size_t)kb * FBN * DDIM;
        #pragma unroll
        for (int it = 0; it < (FBN * DDIM) / (4 * NT); it++) {
            int e = (tid + it * NT) * 4;
            int r = e >> 7, c = e & 127;
            *(float4*)(sK + r * SQS + c) = *(const float4*)(Kb + e);
            *(float4*)(sV + r * DDIM + c) = *(const float4*)(Vb + e);
        }
        __syncthreads();

        float sacc[4][4];
        #pragma unroll
        for (int j = 0; j < 4; j++)
            #pragma unroll
            for (int i = 0; i < 4; i++) sacc[j][i] = 0.f;

        #pragma unroll 4
        for (int d0 = 0; d0 < DDIM; d0 += 4) {
            float4 aq[4], bk[4];
            #pragma unroll
            for (int j = 0; j < 4; j++)
                aq[j] = *(const float4*)(sQ + (4 * ty + j) * SQS + d0);
            #pragma unroll
            for (int i = 0; i < 4; i++)
                bk[i] = *(const float4*)(sK + (tx + 16 * i) * SQS + d0);
            #pragma unroll
            for (int j = 0; j < 4; j++)
                #pragma unroll
                for (int i = 0; i < 4; i++)
                    sacc[j][i] += aq[j].x * bk[i].x + aq[j].y * bk[i].y
                                + aq[j].z * bk[i].z + aq[j].w * bk[i].w;
        }
        __syncthreads();

        uint32_t baseIdx = ((uint32_t)bh << 22) | ((uint32_t)q0 << 11)
                         | (uint32_t)(kb * FBN);
        #pragma unroll
        for (int j = 0; j < 4; j++) {
            #pragma unroll
            for (int i = 0; i < 4; i++) {
                float ex = __expf(sacc[j][i] * scale);
                dsum[j] += ex;
                uint32_t idx = baseIdx + ((uint32_t)(4 * ty + j) << 11)
                             + (uint32_t)(tx + 16 * i);
                uint32_t w = tf_word(idx);
                sP[(4 * ty + j) * SPS + (tx + 16 * i)] = (w & 0x80000000u) ? 0.f : ex;
            }
        }
        __syncthreads();

        #pragma unroll 2
        for (int c0 = 0; c0 < FBN; c0 += 4) {
            float4 p4[4];
            #pragma unroll
            for (int j = 0; j < 4; j++)
                p4[j] = *(const float4*)(sP + (4 * ty + j) * SPS + c0);
            #pragma unroll
            for (int cc = 0; cc < 4; cc++) {
                float bb[8];
                #pragma unroll
                for (int i = 0; i < 8; i++)
                    bb[i] = sV[(c0 + cc) * DDIM + tx + 16 * i];
                #pragma unroll
                for (int j = 0; j < 4; j++) {
                    float pj = ((const float*)&p4[j])[cc];
                    #pragma unroll
                    for (int i = 0; i < 8; i++)
                        acc[j][i] += pj * bb[i];
                }
            }
        }
    }

    __syncthreads();
    #pragma unroll
    for (int j = 0; j < 4; j++)
        sP[(4 * ty + j) * SPS + tx] = dsum[j];
    __syncthreads();

    #pragma unroll
    for (int j = 0; j < 4; j++) {
        float s = 0.f;
        #pragma unroll
        for (int t = 0; t < 16; t++) s += sP[(4 * ty + j) * SPS + t];
        float rs = 2.0f / s;
        size_t orow = ((size_t)bh * SS + (size_t)(q0 + 4 * ty + j)) * DDIM;
        #pragma unroll
        for (int i = 0; i < 8; i++)
            Og[orow + tx + 16 * i] = acc[j][i] * rs;
    }
}

#define FB_SMEM ((2 * FBM * SQS + FBN * DDIM) * 4)

// ===========================================================================
// common helpers
// ===========================================================================
#define BM 128
#define BN 128
#define NKB (SS / BN)            /* 16 kv tiles */

static __device__ __forceinline__ uint32_t smem_u32(const void* p) {
    uint32_t a;
    asm("{ .reg .u64 t; cvta.to.shared.u64 t, %1; cvt.u32.u64 %0, t; }" : "=r"(a) : "l"(p));
    return a;
}
static __device__ __forceinline__ uint32_t swz(uint32_t o) { return o ^ ((o >> 3) & 0x70u); }
// blocked SW128 K-major layout, nrows=128: atom = 8 rows x 64 elems (1024B)
static __device__ __forceinline__ uint32_t koff(int n, int k) {
    return ((uint32_t)((n >> 3) + ((k >> 6) << 4)) << 10)
         + (((uint32_t)n & 7u) << 7) + (((uint32_t)k & 63u) << 1);
}
static __device__ __forceinline__ uint32_t prmt_hi(uint32_t a, uint32_t b) {
    uint32_t r; asm("prmt.b32 %0,%1,%2,0x7632;" : "=r"(r) : "r"(a), "r"(b)); return r;
}
static __device__ __forceinline__ float trunc_bf(float x) {
    return __uint_as_float(__float_as_uint(x) & 0xffff0000u);
}
static __device__ __forceinline__ uint32_t pack_bf2(float hi_elem, float lo_elem) {
    uint32_t r; asm("cvt.rn.bf16x2.f32 %0,%1,%2;" : "=r"(r) : "f"(hi_elem), "f"(lo_elem)); return r;
}
// fp16x2 pack: hi_elem -> high 16 bits, lo_elem -> low 16 bits
static __device__ __forceinline__ uint32_t pack_f16(float hi_elem, float lo_elem) {
    uint32_t r; asm("cvt.rn.f16x2.f32 %0,%1,%2;" : "=r"(r) : "f"(hi_elem), "f"(lo_elem)); return r;
}
static __device__ __forceinline__ float ex2f(float x) {
    float r; asm("ex2.approx.f32 %0, %1;" : "=f"(r) : "f"(x)); return r;
}

// blob tile layout (96KB per tile): KHI 32K | KLO 32K | V(fp16) 32K
#define TILE_BYTES 98304
#define TILE_K 0
#define TILE_V 65536

// main-kernel smem map
#define SM_K0   0               /* KHI0 | KLO0, 64KB */
#define SM_K1   65536           /* KHI1 | KLO1, 64KB */
#define SM_V    131072          /* V fp16, 32KB */
#define SM_DSUM 163840          /* 128 rows x 8 octs x 4B = 4096 */
#define SM_TPTR 167936
#define SM_MB1  167944
#define SM_MB2  167952
#define TC_SMEM 168064

// pre-converted K(bf16 hi/lo) + V(fp16) tiles: 32 bh x 16 tiles x 96KB = 48 MiB
__device__ __align__(1024) unsigned char g_blob[32 * 16 * TILE_BYTES];

// ===========================================================================
// pre-kernel: fp32 K -> bf16 hi/lo, fp32 V -> fp16; MMA-swizzled tile blobs
// ===========================================================================
__global__ __launch_bounds__(256)
void prep_kv_kernel(const float* __restrict__ Kg, const float* __restrict__ Vg) {
    extern __shared__ __align__(16) unsigned char vs[];   // 32KB: V fp16 staged
    const int tile = blockIdx.x;            // bh*16 + kb
    const int bh = tile >> 4, kb = tile & 15;
    const int tid = threadIdx.x;
    const float* Kb = Kg + ((size_t)bh * SS + (size_t)kb * BN) * DDIM;
    const float* Vb = Vg + ((size_t)bh * SS + (size_t)kb * BN) * DDIM;
    unsigned char* out = g_blob + (size_t)tile * TILE_BYTES;

    #pragma unroll
    for (int it = 0; it < 16; it++) {
        int idx = it * 256 + tid;           // float4 index, 4096 total
        int n = idx >> 5, k = (idx & 31) * 4;
        float4 u = *(const float4*)(Kb + n * DDIM + k);
        uint32_t h0 = prmt_hi(__float_as_uint(u.x), __float_as_uint(u.y));
        uint32_t h1 = prmt_hi(__float_as_uint(u.z), __float_as_uint(u.w));
        uint32_t l0 = pack_bf2(u.y - trunc_bf(u.y), u.x - trunc_bf(u.x));
        uint32_t l1 = pack_bf2(u.w - trunc_bf(u.w), u.z - trunc_bf(u.z));
        uint32_t o = swz(koff(n, k));
        *(uint2*)(out + TILE_K + o)         = make_uint2(h0, h1);
        *(uint2*)(out + TILE_K + 32768 + o) = make_uint2(l0, l1);
    }
    // V^T: [128 d rows, 128 kv cols] fp16, staged in smem then linear copy-out
    int w = tid >> 5, lid = tid & 31;
    #pragma unroll
    for (int i = 0; i < 8; i++) {
        int p = w * 8 + i;                  // kv pair 0..63
        #pragma unroll
        for (int j = 0; j < 4; j++) {
            int d = lid + 32 * j;
            float f0 = Vb[(2 * p) * DDIM + d];
            float f1 = Vb[(2 * p + 1) * DDIM + d];
            uint32_t hv = pack_f16(f1, f0);
            uint32_t o = swz(koff(d, 2 * p));
            *(uint32_t*)(vs + o) = hv;
        }
    }
    __syncthreads();
    #pragma unroll
    for (int i = 0; i < 8; i++) {
        int e = (i * 256 + tid) * 16;
        *(float4*)(out + TILE_V + e) = *(const float4*)(vs + e);
    }
}

// ===========================================================================
// tcgen05 kernel — only real on the sm_103a pass
// ===========================================================================
#if !defined(__CUDA_ARCH__) || defined(__CUDA_ARCH_FEAT_SM103_ALL) || \
    (defined(__CUDA_ARCH_SPECIFIC__) && (__CUDA_ARCH_SPECIFIC__ >= 1000))
#define TC_PATH_COMPILED 1
#else
#define TC_PATH_COMPILED 0
#endif
#if defined(__CUDA_ARCH__) && TC_PATH_COMPILED
#define TC_DEV 1
#else
#define TC_DEV 0
#endif

// TMEM map: QHI 0, QLO 64, S 128 (128 cols), P(fp16) 256 (64 cols), O 384 (128)
#define T_QHI 0
#define T_QLO 64
#define T_S   128
#define T_P   256
#define T_O   384
#define TMEM_COLS 512

#define IDESC_BF16 0x8200490u   /* kind::f16, bf16 x bf16 -> f32, M=128, N=128 */
#define IDESC_FP16 0x8200010u   /* kind::f16, fp16 x fp16 -> f32, M=128, N=128 */

static constexpr uint64_t DESC_BASE =
    (uint64_t(2) << 61) | (uint64_t(1) << 46) | (uint64_t(64) << 32) | (uint64_t(1) << 16);
static __device__ __forceinline__ uint64_t mk_desc(uint32_t addr) {
    return DESC_BASE | ((uint64_t)(addr >> 4) & 0x3FFFull);
}

#if TC_DEV
static __device__ __forceinline__ void mma_f16(uint32_t d, uint32_t a, uint64_t bdesc,
                                               uint32_t idesc, int acc) {
    asm volatile(
        "{\n\t.reg .pred p;\n\tsetp.ne.u32 p,%5,0;\n\t"
        "tcgen05.mma.cta_group::1.kind::f16 [%0],[%1],%2,%3,{%4,%4,%4,%4},p;\n\t}"
        :: "r"(d), "r"(a), "l"(bdesc), "r"(idesc), "r"(0u), "r"((uint32_t)acc) : "memory");
}

#define TMEM_ALLOC(sa, n)  asm volatile("tcgen05.alloc.cta_group::1.sync.aligned.shared::cta.b32 [%0], %1;" :: "r"(sa), "r"((uint32_t)(n)) : "memory")
#define TMEM_DEALLOC(t, n) asm volatile("tcgen05.dealloc.cta_group::1.sync.aligned.b32 %0, %1;" :: "r"(t), "r"((uint32_t)(n)))
#define TMEM_RELINQ()      asm volatile("tcgen05.relinquish_alloc_permit.cta_group::1.sync.aligned;")
#define TC_COMMIT(mb)      asm volatile("tcgen05.commit.cta_group::1.mbarrier::arrive::one.shared::cluster.b64 [%0];" :: "r"(mb) : "memory")
#define TC_WAIT_LD()       asm volatile("tcgen05.wait::ld.sync.aligned;" ::: "memory")
#define TC_WAIT_ST()       asm volatile("tcgen05.wait::st.sync.aligned;" ::: "memory")
#define TC_FENCE_BEFORE()  asm volatile("tcgen05.fence::before_thread_sync;" ::: "memory")
#define TC_FENCE_AFTER()   asm volatile("tcgen05.fence::after_thread_sync;" ::: "memory")
#define MBAR_INIT(mb, c)   asm volatile("mbarrier.init.shared.b64 [%0], %1;" :: "r"(mb), "r"((uint32_t)(c)) : "memory")
#define CP_ASYNC16(dst, src) asm volatile("cp.async.cg.shared.global [%0], [%1], 16;" :: "r"(dst), "l"(src) : "memory")
#define CP_COMMIT()        asm volatile("cp.async.commit_group;" ::: "memory")
#define CP_WAIT0()         asm volatile("cp.async.wait_group 0;" ::: "memory")
#define FENCE_PROXY()      asm volatile("fence.proxy.async.shared::cta;" ::: "memory")

static __device__ __forceinline__ void mbar_wait(uint32_t mb, uint32_t parity) {
    asm volatile(
        "{\n\t.reg .pred P;\n\t"
        "W%=:\n\tmbarrier.try_wait.parity.acquire.cta.shared::cta.b64 P, [%0], %1, 0x989680;\n\t"
        "@P bra.uni D%=;\n\tbra.uni W%=;\n\tD%=:\n\t}"
        :: "r"(mb), "r"(parity) : "memory");
}

#define LDTM_X16(r, a) \
    asm volatile("tcgen05.ld.sync.aligned.32x32b.x16.b32 " \
        "{%0,%1,%2,%3,%4,%5,%6,%7,%8,%9,%10,%11,%12,%13,%14,%15}, [%16];" \
        : "=r"((r)[0]),"=r"((r)[1]),"=r"((r)[2]),"=r"((r)[3]),"=r"((r)[4]),"=r"((r)[5]),"=r"((r)[6]),"=r"((r)[7]), \
          "=r"((r)[8]),"=r"((r)[9]),"=r"((r)[10]),"=r"((r)[11]),"=r"((r)[12]),"=r"((r)[13]),"=r"((r)[14]),"=r"((r)[15]) \
        : "r"(a))

#define STTM_X8(a, r) \
    asm volatile("tcgen05.st.sync.aligned.32x32b.x8.b32 [%0], " \
        "{%1,%2,%3,%4,%5,%6,%7,%8};" \
        :: "r"(a), \
          "r"((r)[0]),"r"((r)[1]),"r"((r)[2]),"r"((r)[3]),"r"((r)[4]),"r"((r)[5]),"r"((r)[6]),"r"((r)[7]) \
        : "memory")

#define STTM_X16(a, r) \
    asm volatile("tcgen05.st.sync.aligned.32x32b.x16.b32 [%0], " \
        "{%1,%2,%3,%4,%5,%6,%7,%8,%9,%10,%11,%12,%13,%14,%15,%16};" \
        :: "r"(a), \
          "r"((r)[0]),"r"((r)[1]),"r"((r)[2]),"r"((r)[3]),"r"((r)[4]),"r"((r)[5]),"r"((r)[6]),"r"((r)[7]), \
          "r"((r)[8]),"r"((r)[9]),"r"((r)[10]),"r"((r)[11]),"r"((r)[12]),"r"((r)[13]),"r"((r)[14]),"r"((r)[15]) \
        : "memory")

// copy `bytes` from gmem to smem, threads 0-255, 16B units, coalesced
template <int BYTES>
static __device__ __forceinline__ void copy_gang(uint32_t dst, const unsigned char* src, int t) {
    #pragma unroll
    for (int i = 0; i < BYTES / (256 * 16); i++) {
        uint32_t off = (uint32_t)((i * 256 + t) * 16);
        CP_ASYNC16(dst + off, src + off);
    }
}

// mask bits for 16 consecutive kv columns starting at index `base`
static __device__ __forceinline__ uint32_t mask16(uint32_t base) {
    uint32_t m = 0;
    #pragma unroll 4
    for (int t = 0; t < 16; t++)
        m |= (tf_word(base + t) >> 31) << t;
    return m;
}

// GEMM1: S = Q K^T (3 bf16-split passes), K tile in smem buf sbuf
static __device__ __forceinline__ void issue_g1(uint32_t tmem, uint32_t sb, int sbuf) {
    const int DOFF[8] = {0, 2, 4, 6, 1024, 1026, 1028, 1030};
    uint32_t kb_addr = sb + (sbuf ? SM_K1 : SM_K0);
    uint64_t dh = mk_desc(kb_addr);
    uint64_t dl = mk_desc(kb_addr + 32768);
    #pragma unroll
    for (int ks = 0; ks < 8; ks++)
        mma_f16(tmem + T_S, tmem + T_QHI + ks * 8, dh + DOFF[ks], IDESC_BF16, ks != 0);
    #pragma unroll
    for (int ks = 0; ks < 8; ks++)
        mma_f16(tmem + T_S, tmem + T_QHI + ks * 8, dl + DOFF[ks], IDESC_BF16, 1);
    #pragma unroll
    for (int ks = 0; ks < 8; ks++)
        mma_f16(tmem + T_S, tmem + T_QLO + ks * 8, dh + DOFF[ks], IDESC_BF16, 1);
}

// GEMM2: O += P(fp16) V(fp16) — single pass, V tile in the smem V buffer
static __device__ __forceinline__ void issue_g2(uint32_t tmem, uint32_t sb, int first) {
    const int DOFF[8] = {0, 2, 4, 6, 1024, 1026, 1028, 1030};
    uint64_t dv = mk_desc(sb + SM_V);
    #pragma unroll
    for (int ks = 0; ks < 8; ks++)
        mma_f16(tmem + T_O, tmem + T_P + ks * 8, dv + DOFF[ks], IDESC_FP16, !(first && ks == 0));
}
#endif  // TC_DEV

__global__ __launch_bounds__(1024, 1)
void attn_tc_kernel(const float* __restrict__ Qg, float* __restrict__ Og) {
#if TC_DEV
    extern __shared__ __align__(1024) char smem[];
    const uint32_t sb = smem_u32(smem);
    const int tid = threadIdx.x;
    const int w = tid >> 5, lane = tid & 31;
    const int sub = w & 3, oct = w >> 2;      // oct = 16-col slice index 0..7
    const int row = sub * 32 + lane;
    const int bh = blockIdx.y;
    const int q0 = blockIdx.x * BM;
    const float* Qp = Qg + ((size_t)bh * SS + q0) * DDIM;
    const unsigned char* blob = g_blob + (size_t)(bh * NKB) * TILE_BYTES;

    if (w == 0) TMEM_ALLOC(sb + SM_TPTR, TMEM_COLS);
    if (tid == 0) { MBAR_INIT(sb + SM_MB1, 1); MBAR_INIT(sb + SM_MB2, 1); }
    __syncthreads();
    uint32_t tmem;
    asm volatile("ld.shared.b32 %0, [%1];" : "=r"(tmem) : "r"(sb + SM_TPTR));

    // per-(thread,iter) mask base: columns oct*16.. within tile j at j*BN
    const uint32_t mbase0 = ((uint32_t)bh << 22) | ((uint32_t)(q0 + row) << 11)
                          | (uint32_t)(oct * 16);

    // ---- prologue: K(0) copy (threads 0-255) + Q -> TMEM (threads 0-127) ----
    if (tid < 256) { copy_gang<65536>(sb + SM_K0, blob + TILE_K, tid); CP_COMMIT(); }
    if (tid < 128) {
        const float* qr = Qp + tid * DDIM;
        uint32_t woff = ((uint32_t)((tid >> 5) & 3)) << 21;
        #pragma unroll
        for (int hb = 0; hb < 4; hb++) {
            uint32_t hi[16], lo[16];
            #pragma unroll
            for (int c4 = 0; c4 < 8; c4++) {
                float4 u = *(const float4*)(qr + hb * 32 + c4 * 4);
                hi[2 * c4]     = prmt_hi(__float_as_uint(u.x), __float_as_uint(u.y));
                hi[2 * c4 + 1] = prmt_hi(__float_as_uint(u.z), __float_as_uint(u.w));
                lo[2 * c4]     = pack_bf2(u.y - trunc_bf(u.y), u.x - trunc_bf(u.x));
                lo[2 * c4 + 1] = pack_bf2(u.w - trunc_bf(u.w), u.z - trunc_bf(u.z));
            }
            STTM_X16(tmem + T_QHI + hb * 16 + woff, hi);
            STTM_X16(tmem + T_QLO + hb * 16 + woff, lo);
        }
        TC_WAIT_ST();
    }
    // mask(0) — overlaps the copy/convert waits
    uint32_t mbits = mask16(mbase0);
    CP_WAIT0();
    FENCE_PROXY();
    TC_FENCE_BEFORE();
    __syncthreads();
    if (tid == 0) {
        TC_FENCE_AFTER();
        issue_g1(tmem, sb, 0);
        TC_COMMIT(sb + SM_MB1);
    }

    // exp(x/sqrt(128)) == ex2(x * log2(e)/sqrt(128))
    const float scale2 = 0.12752966448211458f;
    float dsum0 = 0.f, dsum1 = 0.f;   // two chains: halve the serial FADD depth

    #pragma unroll 2
    for (int j = 0; j < NKB; j++) {
        // A: copy gang — after G2(j-1) done: V(j) -> V buffer, K(j+1) -> other K buf
        if (tid < 256) {
            if (j > 0) mbar_wait(sb + SM_MB2, (j - 1) & 1);
            copy_gang<32768>(sb + SM_V, blob + (size_t)j * TILE_BYTES + TILE_V, tid);
            if (j < NKB - 1)
                copy_gang<65536>(sb + (((j + 1) & 1) ? SM_K1 : SM_K0),
                                 blob + (size_t)(j + 1) * TILE_BYTES + TILE_K, tid);
            CP_COMMIT();
        }
        // B: S ready -> LDTM ISSUE (no wait yet)
        mbar_wait(sb + SM_MB1, j & 1);
        TC_FENCE_AFTER();
        uint32_t sr[16];
        LDTM_X16(sr, tmem + T_S + oct * 16);
        // C: threefry mask for iteration j+1 — fills the TMEM-read drain
        uint32_t mb_nxt = 0;
        if (j < NKB - 1)
            mb_nxt = mask16(mbase0 + (uint32_t)((j + 1) * BN));
        TC_WAIT_LD();
        TC_FENCE_BEFORE();
        // D: copies done + visible to MMA; S tile drained
        CP_WAIT0();
        FENCE_PROXY();
        __syncthreads();
        // E: launch next GEMM1 into freed S
        if (tid == 0 && j < NKB - 1) {
            TC_FENCE_AFTER();
            issue_g1(tmem, sb, (j + 1) & 1);
            TC_COMMIT(sb + SM_MB1);
        }
        // F: exp + mask(j) -> P (single fp16 pack per pair)
        uint32_t ph[8];
        #pragma unroll
        for (int t2 = 0; t2 < 8; t2++) {
            float e0 = ex2f(__uint_as_float(sr[2 * t2]) * scale2);
            float e1 = ex2f(__uint_as_float(sr[2 * t2 + 1]) * scale2);
            dsum0 += e0;
            dsum1 += e1;
            float p0 = (mbits & (1u << (2 * t2)))     ? 0.f : e0;
            float p1 = (mbits & (1u << (2 * t2 + 1))) ? 0.f : e1;
            ph[t2] = pack_f16(p1, p0);
        }
        mbits = mb_nxt;
        uint32_t woff = ((uint32_t)sub) << 21;
        STTM_X8(tmem + T_P + oct * 8 + woff, ph);
        TC_WAIT_ST();
        TC_FENCE_BEFORE();
        __syncthreads();
        // G: launch GEMM2 (single fp16 pass)
        if (tid == 0) {
            TC_FENCE_AFTER();
            issue_g2(tmem, sb, j == 0);
            TC_COMMIT(sb + SM_MB2);
        }
    }

    mbar_wait(sb + SM_MB2, (NKB - 1) & 1);
    TC_FENCE_AFTER();

    // denominator reduce across the 8 column slices
    ((float*)(smem + SM_DSUM))[row * 8 + oct] = dsum0 + dsum1;
    __syncthreads();
    float tot = 0.f;
    #pragma unroll
    for (int i = 0; i < 8; i++)
        tot += ((float*)(smem + SM_DSUM))[row * 8 + i];
    float rs = 2.0f / tot;   // dropout 1/(1-p)=2 folded in

    uint32_t orv[16];
    LDTM_X16(orv, tmem + T_O + oct * 16);
    TC_WAIT_LD();
    TC_FENCE_BEFORE();
    size_t orow = ((size_t)bh * SS + (size_t)(q0 + row)) * DDIM;
    #pragma unroll
    for (int t = 0; t < 16; t++)
        Og[orow + oct * 16 + t] = __uint_as_float(orv[t]) * rs;

    __syncthreads();
    if (w == 0) { TMEM_RELINQ(); TMEM_DEALLOC(tmem, TMEM_COLS); }
#else
    (void)Qg; (void)Og;
#endif
}

// ===========================================================================
// host dispatch
// ===========================================================================
extern "C" void kernel_launch(void* const* d_in, const int* in_sizes, int n_in,
                              void* d_out, int out_size) {
    (void)in_sizes; (void)n_in; (void)out_size;
    const float* Q = (const float*)d_in[0];
    const float* K = (const float*)d_in[1];
    const float* V = (const float*)d_in[2];
    float* O = (float*)d_out;

    cudaFuncAttributes fa;
    bool tc_ok = (cudaFuncGetAttributes(&fa, attn_tc_kernel) == cudaSuccess)
               && fa.numRegs > 40;

    if (tc_ok) {
        cudaFuncSetAttribute(prep_kv_kernel,
                             cudaFuncAttributeMaxDynamicSharedMemorySize, 32768);
        prep_kv_kernel<<<512, 256, 32768>>>(K, V);
        cudaFuncSetAttribute(attn_tc_kernel,
                             cudaFuncAttributeMaxDynamicSharedMemorySize, TC_SMEM);
        dim3 grid(SS / BM, 32);
        attn_tc_kernel<<<grid, 1024, TC_SMEM>>>(Q, O);
    } else {
        cudaFuncSetAttribute(attn_dropout_kernel,
                             cudaFuncAttributeMaxDynamicSharedMemorySize, FB_SMEM);
        dim3 grid(SS / FBM, 32);
        attn_dropout_kernel<<<grid, NT, FB_SMEM>>>(Q, K, V, O);
    }
}